// round 10
// baseline (speedup 1.0000x reference)
#include <cuda_runtime.h>
#include <cuda_bf16.h>
#include <cstdint>

// Problem constants
#define BATCH 2
#define SLEN  2048
#define DMODEL 4096
#define NHEAD 32
#define NKVH  8
#define HDIM  128
#define NTOK  (BATCH*SLEN)          // 4096
#define QKVW  6144                  // 4096 q + 1024 k + 1024 v
#define ATT_SCALE 0.08838834764831845f
#define QMAX 32512.0f               // 16-bit fixed-point clamp (so hi byte fits int8)

typedef signed char s8;

// ---------------------------------------------------------------------------
// Scratch (allocation-free rule: __device__ globals)
// ---------------------------------------------------------------------------
__device__ float g_amax[8];                                  // 0=x 1=wq 2=wk 3=wv 4=wo 5=att
__device__ s8 g_xq1[(size_t)NTOK * DMODEL];
__device__ s8 g_xq0[(size_t)NTOK * DMODEL];
__device__ s8 g_wq1[(size_t)QKVW * DMODEL];                  // fused wq|wk|wv rows
__device__ s8 g_wq0[(size_t)QKVW * DMODEL];
__device__ s8 g_woq1[(size_t)DMODEL * DMODEL];
__device__ s8 g_woq0[(size_t)DMODEL * DMODEL];
__device__ s8 g_aq1[(size_t)NTOK * DMODEL];
__device__ s8 g_aq0[(size_t)NTOK * DMODEL];
__device__ float g_att[(size_t)NTOK * DMODEL];               // flash output (fp32)
__device__ __nv_bfloat16 g_qkvhi[(size_t)NTOK * QKVW];       // flash operands
__device__ __nv_bfloat16 g_qkvlo[(size_t)NTOK * QKVW];

// ---------------------------------------------------------------------------
// Helpers
// ---------------------------------------------------------------------------
__device__ __forceinline__ uint32_t smem_u32(const void* p) {
    uint32_t a;
    asm("{ .reg .u64 t; cvta.to.shared.u64 t, %1; cvt.u32.u64 %0, t; }" : "=r"(a) : "l"(p));
    return a;
}
__device__ __forceinline__ void cp16(uint32_t dst, const void* src) {
    asm volatile("cp.async.cg.shared.global [%0], [%1], 16;" :: "r"(dst), "l"(src));
}
__device__ __forceinline__ void ldsm_x4(uint32_t* r, uint32_t addr) {
    asm volatile("ldmatrix.sync.aligned.m8n8.x4.shared.b16 {%0,%1,%2,%3}, [%4];"
                 : "=r"(r[0]), "=r"(r[1]), "=r"(r[2]), "=r"(r[3]) : "r"(addr));
}
__device__ __forceinline__ void ldsm_x4t(uint32_t* r, uint32_t addr) {
    asm volatile("ldmatrix.sync.aligned.m8n8.x4.trans.shared.b16 {%0,%1,%2,%3}, [%4];"
                 : "=r"(r[0]), "=r"(r[1]), "=r"(r[2]), "=r"(r[3]) : "r"(addr));
}
__device__ __forceinline__ void mma16816(float* d, const uint32_t* a, const uint32_t* b) {
    asm volatile("mma.sync.aligned.m16n8k16.row.col.f32.bf16.bf16.f32 "
                 "{%0,%1,%2,%3}, {%4,%5,%6,%7}, {%8,%9}, {%0,%1,%2,%3};"
                 : "+f"(d[0]), "+f"(d[1]), "+f"(d[2]), "+f"(d[3])
                 : "r"(a[0]), "r"(a[1]), "r"(a[2]), "r"(a[3]), "r"(b[0]), "r"(b[1]));
}
__device__ __forceinline__ void imma16832(int* d, const uint32_t* a, const uint32_t* b) {
    asm volatile("mma.sync.aligned.m16n8k32.row.col.s32.s8.s8.s32 "
                 "{%0,%1,%2,%3}, {%4,%5,%6,%7}, {%8,%9}, {%0,%1,%2,%3};"
                 : "+r"(d[0]), "+r"(d[1]), "+r"(d[2]), "+r"(d[3])
                 : "r"(a[0]), "r"(a[1]), "r"(a[2]), "r"(a[3]), "r"(b[0]), "r"(b[1]));
}
__device__ __forceinline__ uint32_t pack_hl(float f0, float f1, uint32_t& lo) {
    __nv_bfloat16 h0 = __float2bfloat16(f0), h1 = __float2bfloat16(f1);
    __nv_bfloat16 l0 = __float2bfloat16(f0 - __bfloat162float(h0));
    __nv_bfloat16 l1 = __float2bfloat16(f1 - __bfloat162float(h1));
    __nv_bfloat162 hp(h0, h1), lp(l0, l1);
    lo = *(uint32_t*)&lp;
    return *(uint32_t*)&hp;
}

// ---------------------------------------------------------------------------
// amax init / absmax / quantize
// ---------------------------------------------------------------------------
__global__ void init_amax() { if (threadIdx.x < 8) g_amax[threadIdx.x] = 0.f; }

__global__ void absmax_k(const float* __restrict__ src, int n4, int slot) {
    float m = 0.f;
    for (int i = blockIdx.x * 256 + threadIdx.x; i < n4; i += gridDim.x * 256) {
        float4 v = ((const float4*)src)[i];
        m = fmaxf(m, fmaxf(fmaxf(fabsf(v.x), fabsf(v.y)), fmaxf(fabsf(v.z), fabsf(v.w))));
    }
#pragma unroll
    for (int o = 16; o; o >>= 1) m = fmaxf(m, __shfl_xor_sync(0xffffffffu, m, o));
    if ((threadIdx.x & 31) == 0) atomicMax((int*)&g_amax[slot], __float_as_int(m));
}

__device__ __forceinline__ void q1(float x, float inv, s8& h, s8& l) {
    int xi = __float2int_rn(x * inv);
    xi = max(-32512, min(32512, xi));
    int x1 = (xi + 128) >> 8;
    h = (s8)x1;
    l = (s8)(xi - (x1 << 8));
}
__global__ void quant_k(const float* __restrict__ src, s8* __restrict__ d1,
                        s8* __restrict__ d0, int n, int slot) {
    int i = (blockIdx.x * 256 + threadIdx.x) * 4;
    if (i >= n) return;
    float inv = QMAX / g_amax[slot];
    float4 v = *(const float4*)(src + i);
    char4 h, l;
    q1(v.x, inv, h.x, l.x); q1(v.y, inv, h.y, l.y);
    q1(v.z, inv, h.z, l.z); q1(v.w, inv, h.w, l.w);
    *(char4*)(d1 + i) = h;
    *(char4*)(d0 + i) = l;
}

// ---------------------------------------------------------------------------
// int8 IMMA fixed-point GEMM:
// C = s_a*s_b*( (A1 B1^T)<<16 + (A1 B0^T + A0 B1^T)<<8 )   [x0y0 dropped]
// A,B row-major int8, K contiguous. CTA 128x128, K-chunk 64, 8 warps (64x32
// warp tile), 3-stage cp.async pipeline. grid: (M/128, N/128).
// Epilogue: fp32 C or bf16 hi/lo split.
// ---------------------------------------------------------------------------
#define IROWB  80                     // 64 data bytes + 16 pad
#define IBUF   (128 * IROWB)          // 10240
#define ISTAGE (4 * IBUF)             // A1|A0|B1|B0 = 40960
#define INST   3
#define IGSMEM (INST * ISTAGE)        // 122880

__global__ __launch_bounds__(256, 1) void gemm_imma_split(
    const s8* __restrict__ A1, const s8* __restrict__ A0,
    const s8* __restrict__ B1, const s8* __restrict__ B0,
    float* __restrict__ C, __nv_bfloat16* __restrict__ Chi, __nv_bfloat16* __restrict__ Clo,
    int K, int ldc, int sa_slot, int sb_slot)
{
    extern __shared__ char dynsm[];
    const uint32_t smb = smem_u32(dynsm);
    const int tid  = threadIdx.x;
    const int wid  = tid >> 5;
    const int lane = tid & 31;
    const int m0 = blockIdx.x * 128;
    const int n0 = blockIdx.y * 128;
    const int nch = K >> 6;           // 64-byte K-chunks

    const s8* srcs[4] = { A1, A0, B1, B0 };
    const int bases[4] = { m0, m0, n0, n0 };

    auto load_stage = [&](int c, int st) {
        const uint32_t sb = smb + st * ISTAGE;
#pragma unroll
        for (int buf = 0; buf < 4; buf++) {
            const s8* src = srcs[buf] + (size_t)bases[buf] * K + c * 64;
#pragma unroll
            for (int i = 0; i < 2; i++) {
                int o = i * 256 + tid;
                int r = o >> 2, s = o & 3;
                cp16(sb + buf * IBUF + r * IROWB + s * 16, src + (size_t)r * K + s * 16);
            }
        }
        asm volatile("cp.async.commit_group;" ::: "memory");
    };

    int a16[4][4][4], a8[4][4][4];
#pragma unroll
    for (int mt = 0; mt < 4; mt++)
#pragma unroll
        for (int nt = 0; nt < 4; nt++)
#pragma unroll
            for (int q = 0; q < 4; q++) { a16[mt][nt][q] = 0; a8[mt][nt][q] = 0; }

    load_stage(0, 0);
    load_stage(1, 1);

    const int wm = (wid >> 2) * 64;            // 0 or 64
    const int wn = (wid & 3) * 32;             // 0,32,64,96
    // validated A x4 pattern (byte-identical layout s8 k32 vs bf16 k16)
    const int arow = lane & 15, acolg = lane >> 4;
    // validated B x4 pattern (2 n8 b-frags per load)
    const int brow = ((lane >> 4) << 3) + (lane & 7);
    const int bkof = ((lane >> 3) & 1) * 16;

    for (int c = 0; c < nch; c++) {
        if (c + 1 < nch) asm volatile("cp.async.wait_group 1;" ::: "memory");
        else             asm volatile("cp.async.wait_group 0;" ::: "memory");
        __syncthreads();
        if (c + 2 < nch) load_stage(c + 2, (c + 2) % INST);

        const uint32_t sb  = smb + (c % INST) * ISTAGE;
        const uint32_t A1B = sb;
        const uint32_t A0B = sb + IBUF;
        const uint32_t B1B = sb + 2 * IBUF;
        const uint32_t B0B = sb + 3 * IBUF;

#pragma unroll
        for (int ks = 0; ks < 2; ks++) {
            const int kb = ks * 32;            // 32-byte k32 step
            uint32_t x1[4][4], x0[4][4];
#pragma unroll
            for (int mt = 0; mt < 4; mt++) {
                uint32_t ao = (wm + mt * 16 + arow) * IROWB + kb + acolg * 16;
                ldsm_x4(x1[mt], A1B + ao);
                ldsm_x4(x0[mt], A0B + ao);
            }
#pragma unroll
            for (int ng = 0; ng < 2; ng++) {
                uint32_t y1[4], y0[4];
                uint32_t bo = (wn + ng * 16 + brow) * IROWB + kb + bkof;
                ldsm_x4(y1, B1B + bo);
                ldsm_x4(y0, B0B + bo);
#pragma unroll
                for (int hf = 0; hf < 2; hf++) {
                    const int nt = 2 * ng + hf;
#pragma unroll
                    for (int mt = 0; mt < 4; mt++) imma16832(a16[mt][nt], x1[mt], y1 + 2 * hf);
#pragma unroll
                    for (int mt = 0; mt < 4; mt++) imma16832(a8[mt][nt],  x1[mt], y0 + 2 * hf);
#pragma unroll
                    for (int mt = 0; mt < 4; mt++) imma16832(a8[mt][nt],  x0[mt], y1 + 2 * hf);
                }
            }
        }
    }

    const float s = (g_amax[sa_slot] * (1.f / QMAX)) *
                    (g_amax[sb_slot >= 0 ? sb_slot : (n0 < 4096 ? 1 : (n0 < 5120 ? 2 : 3))] * (1.f / QMAX));
    const float s16 = s * 65536.f, s8s = s * 256.f;

#pragma unroll
    for (int mt = 0; mt < 4; mt++) {
        int r0 = m0 + wm + mt * 16 + (lane >> 2);
#pragma unroll
        for (int nt = 0; nt < 4; nt++) {
            int cc = n0 + wn + nt * 8 + (lane & 3) * 2;
            float v[4];
#pragma unroll
            for (int q = 0; q < 4; q++)
                v[q] = fmaf((float)a16[mt][nt][q], s16, (float)a8[mt][nt][q] * s8s);
            if (Chi) {
                uint32_t lo0, lo1;
                uint32_t hi0 = pack_hl(v[0], v[1], lo0);
                uint32_t hi1 = pack_hl(v[2], v[3], lo1);
                *(uint32_t*)(Chi + (size_t)r0 * ldc + cc)       = hi0;
                *(uint32_t*)(Clo + (size_t)r0 * ldc + cc)       = lo0;
                *(uint32_t*)(Chi + (size_t)(r0 + 8) * ldc + cc) = hi1;
                *(uint32_t*)(Clo + (size_t)(r0 + 8) * ldc + cc) = lo1;
            } else {
                *(float2*)(C + (size_t)r0 * ldc + cc)       = make_float2(v[0], v[1]);
                *(float2*)(C + (size_t)(r0 + 8) * ldc + cc) = make_float2(v[2], v[3]);
            }
        }
    }
}

// ---------------------------------------------------------------------------
// RoPE on hi/lo representation, in place on q + k of g_qkvhi/g_qkvlo
// ---------------------------------------------------------------------------
__global__ void rope_hl(__nv_bfloat16* __restrict__ hi, __nv_bfloat16* __restrict__ lo,
                        const float* __restrict__ cosp, const float* __restrict__ sinp)
{
    int idx = blockIdx.x * 256 + threadIdx.x;
    if (idx >= NTOK * 40 * 64) return;
    int p  = idx & 63;
    int h2 = (idx >> 6) % 40;
    int t  = idx / (64 * 40);
    float c  = cosp[(size_t)t * 64 + p];
    float sn = sinp[(size_t)t * 64 + p];
    size_t base = (size_t)t * QKVW + (h2 < 32 ? h2 * HDIM : 4096 + (h2 - 32) * HDIM) + 2 * p;
    float t0 = __bfloat162float(hi[base])     + __bfloat162float(lo[base]);
    float t1 = __bfloat162float(hi[base + 1]) + __bfloat162float(lo[base + 1]);
    float r0 = t0 * c - t1 * sn;
    float r1 = t0 * sn + t1 * c;
    uint32_t lp;
    uint32_t hp = pack_hl(r0, r1, lp);
    *(uint32_t*)(hi + base) = hp;
    *(uint32_t*)(lo + base) = lp;
}

// ---------------------------------------------------------------------------
// Flash attention, tensor-core (bf16 3-term split), causal, GQA 4:1.
// Same as R6/R7 (validated) except epilogue writes fp32 att.
// ---------------------------------------------------------------------------
#define FROW    272
#define FQLO    (128 * FROW)
#define FSTAGE0 (2 * 128 * FROW)
#define FSTAGESZ (4 * 64 * FROW)
#define FK_HI 0
#define FK_LO (64 * FROW)
#define FV_HI (2 * 64 * FROW)
#define FV_LO (3 * 64 * FROW)
#define FSMEM (FSTAGE0 + 2 * FSTAGESZ)   // 208896 B

__global__ __launch_bounds__(256, 1) void flash_mma(
    const __nv_bfloat16* __restrict__ qhi, const __nv_bfloat16* __restrict__ qlo,
    float* __restrict__ attp)
{
    extern __shared__ char fsm[];
    const uint32_t smb = smem_u32(fsm);
    const int qt = 15 - (int)blockIdx.x;
    const int h  = blockIdx.y;
    const int b  = blockIdx.z;
    const int kvh = h >> 2;
    const int tid = threadIdx.x, wid = tid >> 5, lane = tid & 31;
    const int nkt = 2 * qt + 2;

    const size_t tokQ = (size_t)b * SLEN + (size_t)qt * 128;
    const __nv_bfloat16* Qhg = qhi + tokQ * QKVW + h * HDIM;
    const __nv_bfloat16* Qlg = qlo + tokQ * QKVW + h * HDIM;
    const size_t kvbase = (size_t)b * SLEN * QKVW + kvh * HDIM;
    const __nv_bfloat16* Khg = qhi + kvbase + 4096;
    const __nv_bfloat16* Klg = qlo + kvbase + 4096;
    const __nv_bfloat16* Vhg = qhi + kvbase + 5120;
    const __nv_bfloat16* Vlg = qlo + kvbase + 5120;

    auto load_kv = [&](int kt, int buf) {
        const uint32_t sb = smb + FSTAGE0 + buf * FSTAGESZ;
#pragma unroll
        for (int i = 0; i < 4; i++) {
            int ch = tid + i * 256;
            int r = ch >> 4, s = ch & 15;
            size_t go = (size_t)(kt * 64 + r) * QKVW + s * 8;
            uint32_t so = r * FROW + s * 16;
            cp16(sb + FK_HI + so, Khg + go);
            cp16(sb + FK_LO + so, Klg + go);
            cp16(sb + FV_HI + so, Vhg + go);
            cp16(sb + FV_LO + so, Vlg + go);
        }
        asm volatile("cp.async.commit_group;" ::: "memory");
    };

#pragma unroll
    for (int i = 0; i < 8; i++) {
        int ch = tid + i * 256;
        int r = ch >> 4, s = ch & 15;
        size_t go = (size_t)r * QKVW + s * 8;
        uint32_t so = r * FROW + s * 16;
        cp16(smb + so,        Qhg + go);
        cp16(smb + FQLO + so, Qlg + go);
    }
    load_kv(0, 0);
    load_kv(1, 1);

    float o[16][4];
#pragma unroll
    for (int ct = 0; ct < 16; ct++)
#pragma unroll
        for (int q = 0; q < 4; q++) o[ct][q] = 0.f;
    float m0 = -1e30f, m1 = -1e30f, l0 = 0.f, l1 = 0.f;

    const uint32_t aAddr0 = smb + (wid * 16 + (lane & 15)) * FROW + (lane >> 4) * 16;
    const int brow = ((lane >> 4) << 3) + (lane & 7);
    const int bkof = ((lane >> 3) & 1) * 16;
    const int vrowl = ((lane >> 3) & 1) * 8 + (lane & 7);
    const int vcof = ((lane >> 4) << 3) * 2;

    for (int kt = 0; kt < nkt; kt++) {
        if (kt + 1 < nkt) asm volatile("cp.async.wait_group 1;" ::: "memory");
        else              asm volatile("cp.async.wait_group 0;" ::: "memory");
        __syncthreads();

        const uint32_t Kb = smb + FSTAGE0 + (kt & 1) * FSTAGESZ;

        float s[8][4];
#pragma unroll
        for (int nt = 0; nt < 8; nt++)
#pragma unroll
            for (int q = 0; q < 4; q++) s[nt][q] = 0.f;

#pragma unroll
        for (int ks = 0; ks < 8; ks++) {
            uint32_t ah[4], al[4];
            ldsm_x4(ah, aAddr0 + ks * 32);
            ldsm_x4(al, aAddr0 + FQLO + ks * 32);
#pragma unroll
            for (int np = 0; np < 4; np++) {
                uint32_t bh[4], bl[4];
                uint32_t ba = Kb + (np * 16 + brow) * FROW + ks * 32 + bkof;
                ldsm_x4(bh, ba + FK_HI);
                ldsm_x4(bl, ba + FK_LO);
                mma16816(s[2 * np],     ah, bh);
                mma16816(s[2 * np],     ah, bl);
                mma16816(s[2 * np],     al, bh);
                mma16816(s[2 * np + 1], ah, bh + 2);
                mma16816(s[2 * np + 1], ah, bl + 2);
                mma16816(s[2 * np + 1], al, bh + 2);
            }
        }

        const bool need_mask = (kt >= 2 * qt);
        const int rg0 = qt * 128 + wid * 16 + (lane >> 2);
#pragma unroll
        for (int nt = 0; nt < 8; nt++) {
#pragma unroll
            for (int q = 0; q < 4; q++) {
                float v = s[nt][q] * ATT_SCALE;
                if (need_mask) {
                    int col = kt * 64 + nt * 8 + (lane & 3) * 2 + (q & 1);
                    int row = rg0 + ((q >> 1) << 3);
                    if (col > row) v = -1e30f;
                }
                s[nt][q] = v;
            }
        }
        float mx0 = -1e30f, mx1 = -1e30f;
#pragma unroll
        for (int nt = 0; nt < 8; nt++) {
            mx0 = fmaxf(mx0, fmaxf(s[nt][0], s[nt][1]));
            mx1 = fmaxf(mx1, fmaxf(s[nt][2], s[nt][3]));
        }
        mx0 = fmaxf(mx0, __shfl_xor_sync(0xffffffffu, mx0, 1));
        mx0 = fmaxf(mx0, __shfl_xor_sync(0xffffffffu, mx0, 2));
        mx1 = fmaxf(mx1, __shfl_xor_sync(0xffffffffu, mx1, 1));
        mx1 = fmaxf(mx1, __shfl_xor_sync(0xffffffffu, mx1, 2));

        float mn0 = fmaxf(m0, mx0), mn1 = fmaxf(m1, mx1);
        float al0 = __expf(m0 - mn0), al1 = __expf(m1 - mn1);
        m0 = mn0; m1 = mn1;
        float rs0 = 0.f, rs1 = 0.f;
#pragma unroll
        for (int nt = 0; nt < 8; nt++) {
            float p0 = __expf(s[nt][0] - mn0);
            float p1 = __expf(s[nt][1] - mn0);
            float p2 = __expf(s[nt][2] - mn1);
            float p3 = __expf(s[nt][3] - mn1);
            s[nt][0] = p0; s[nt][1] = p1; s[nt][2] = p2; s[nt][3] = p3;
            rs0 += p0 + p1; rs1 += p2 + p3;
        }
        rs0 += __shfl_xor_sync(0xffffffffu, rs0, 1);
        rs0 += __shfl_xor_sync(0xffffffffu, rs0, 2);
        rs1 += __shfl_xor_sync(0xffffffffu, rs1, 1);
        rs1 += __shfl_xor_sync(0xffffffffu, rs1, 2);
        l0 = l0 * al0 + rs0;
        l1 = l1 * al1 + rs1;
#pragma unroll
        for (int ct = 0; ct < 16; ct++) {
            o[ct][0] *= al0; o[ct][1] *= al0;
            o[ct][2] *= al1; o[ct][3] *= al1;
        }

#pragma unroll
        for (int kj = 0; kj < 4; kj++) {
            uint32_t ph[4], pl[4];
            ph[0] = pack_hl(s[2 * kj][0],     s[2 * kj][1],     pl[0]);
            ph[1] = pack_hl(s[2 * kj][2],     s[2 * kj][3],     pl[1]);
            ph[2] = pack_hl(s[2 * kj + 1][0], s[2 * kj + 1][1], pl[2]);
            ph[3] = pack_hl(s[2 * kj + 1][2], s[2 * kj + 1][3], pl[3]);
            uint32_t vbase = Kb + (kj * 16 + vrowl) * FROW + vcof;
#pragma unroll
            for (int cp2 = 0; cp2 < 8; cp2++) {
                uint32_t vh[4], vl[4];
                uint32_t va = vbase + cp2 * 32;
                ldsm_x4t(vh, va + FV_HI);
                ldsm_x4t(vl, va + FV_LO);
                mma16816(o[2 * cp2],     ph, vh);
                mma16816(o[2 * cp2],     pl, vh);
                mma16816(o[2 * cp2],     ph, vl);
                mma16816(o[2 * cp2 + 1], ph, vh + 2);
                mma16816(o[2 * cp2 + 1], pl, vh + 2);
                mma16816(o[2 * cp2 + 1], ph, vl + 2);
            }
        }

        __syncthreads();
        if (kt + 2 < nkt) load_kv(kt + 2, kt & 1);
    }

    float inv0 = 1.0f / l0, inv1 = 1.0f / l1;
    size_t trow0 = (size_t)b * SLEN + qt * 128 + wid * 16 + (lane >> 2);
    int colb = h * HDIM + (lane & 3) * 2;
#pragma unroll
    for (int ct = 0; ct < 16; ct++) {
        int col = colb + ct * 8;
        *(float2*)(attp + trow0 * DMODEL + col)       = make_float2(o[ct][0] * inv0, o[ct][1] * inv0);
        *(float2*)(attp + (trow0 + 8) * DMODEL + col) = make_float2(o[ct][2] * inv1, o[ct][3] * inv1);
    }
}

// ---------------------------------------------------------------------------
// Launch. inputs: 0=x 1=mask(all-true) 2=cos 3=sin 4=wq 5=wk 6=wv 7=wo
// ---------------------------------------------------------------------------
extern "C" void kernel_launch(void* const* d_in, const int* in_sizes, int n_in,
                              void* d_out, int out_size)
{
    const float* x    = (const float*)d_in[0];
    const float* cosp = (const float*)d_in[2];
    const float* sinp = (const float*)d_in[3];
    const float* wq   = (const float*)d_in[4];
    const float* wk   = (const float*)d_in[5];
    const float* wv   = (const float*)d_in[6];
    const float* wo   = (const float*)d_in[7];
    float* outp = (float*)d_out;

    s8 *xq1, *xq0, *wq1, *wq0, *woq1, *woq0, *aq1, *aq0;
    float* att;
    __nv_bfloat16 *qkvhi, *qkvlo;
    cudaGetSymbolAddress((void**)&xq1,   g_xq1);
    cudaGetSymbolAddress((void**)&xq0,   g_xq0);
    cudaGetSymbolAddress((void**)&wq1,   g_wq1);
    cudaGetSymbolAddress((void**)&wq0,   g_wq0);
    cudaGetSymbolAddress((void**)&woq1,  g_woq1);
    cudaGetSymbolAddress((void**)&woq0,  g_woq0);
    cudaGetSymbolAddress((void**)&aq1,   g_aq1);
    cudaGetSymbolAddress((void**)&aq0,   g_aq0);
    cudaGetSymbolAddress((void**)&att,   g_att);
    cudaGetSymbolAddress((void**)&qkvhi, g_qkvhi);
    cudaGetSymbolAddress((void**)&qkvlo, g_qkvlo);

    cudaFuncSetAttribute(gemm_imma_split, cudaFuncAttributeMaxDynamicSharedMemorySize, IGSMEM);
    cudaFuncSetAttribute(flash_mma, cudaFuncAttributeMaxDynamicSharedMemorySize, FSMEM);

    const int NX = NTOK * DMODEL;            // 16.7M
    const int NW = DMODEL * DMODEL;          // 16.7M
    const int NK = NKVH * HDIM * DMODEL;     // 4.2M

    init_amax<<<1, 32>>>();
    absmax_k<<<512, 256>>>(x,  NX / 4, 0);
    absmax_k<<<512, 256>>>(wq, NW / 4, 1);
    absmax_k<<<512, 256>>>(wk, NK / 4, 2);
    absmax_k<<<512, 256>>>(wv, NK / 4, 3);
    absmax_k<<<512, 256>>>(wo, NW / 4, 4);
    quant_k<<<NX / 1024, 256>>>(x,  xq1, xq0, NX, 0);
    quant_k<<<NW / 1024, 256>>>(wq, wq1, wq0, NW, 1);
    quant_k<<<NK / 1024, 256>>>(wk, wq1 + (size_t)4096 * DMODEL, wq0 + (size_t)4096 * DMODEL, NK, 2);
    quant_k<<<NK / 1024, 256>>>(wv, wq1 + (size_t)5120 * DMODEL, wq0 + (size_t)5120 * DMODEL, NK, 3);
    quant_k<<<NW / 1024, 256>>>(wo, woq1, woq0, NW, 4);

    // Fused QKV projection (int8 IMMA) -> bf16 hi/lo for flash
    gemm_imma_split<<<dim3(NTOK / 128, QKVW / 128), 256, IGSMEM>>>(
        xq1, xq0, wq1, wq0, nullptr, qkvhi, qkvlo, DMODEL, QKVW, 0, -1);

    // RoPE in hi/lo domain on q and k
    rope_hl<<<(NTOK * 40 * 64) / 256, 256>>>(qkvhi, qkvlo, cosp, sinp);

    // Tensor-core causal GQA attention -> fp32 att
    flash_mma<<<dim3(SLEN / 128, NHEAD, BATCH), 256, FSMEM>>>(qkvhi, qkvlo, att);

    // Quantize attention output, then output projection (int8 IMMA) -> fp32 d_out
    absmax_k<<<512, 256>>>(att, NX / 4, 5);
    quant_k<<<NX / 1024, 256>>>(att, aq1, aq0, NX, 5);
    gemm_imma_split<<<dim3(NTOK / 128, DMODEL / 128), 256, IGSMEM>>>(
        aq1, aq0, woq1, woq0, outp, nullptr, nullptr, DMODEL, DMODEL, 5, 4);
}

// round 11
// speedup vs baseline: 2.1857x; 2.1857x over previous
#include <cuda_runtime.h>
#include <cuda_bf16.h>
#include <cstdint>

// Problem constants
#define BATCH 2
#define SLEN  2048
#define DMODEL 4096
#define NHEAD 32
#define NKVH  8
#define HDIM  128
#define NTOK  (BATCH*SLEN)          // 4096
#define QKVW  6144                  // 4096 q + 1024 k + 1024 v
#define ATT_SCALE 0.08838834764831845f

// ---------------------------------------------------------------------------
// Scratch (allocation-free rule: __device__ globals)
// ---------------------------------------------------------------------------
__device__ __nv_bfloat16 g_xhi[(size_t)NTOK * DMODEL];
__device__ __nv_bfloat16 g_xlo[(size_t)NTOK * DMODEL];
__device__ __nv_bfloat16 g_whi[(size_t)QKVW * DMODEL];   // fused wq|wk|wv rows
__device__ __nv_bfloat16 g_wlo[(size_t)QKVW * DMODEL];
__device__ __nv_bfloat16 g_wohi[(size_t)DMODEL * DMODEL];
__device__ __nv_bfloat16 g_wolo[(size_t)DMODEL * DMODEL];
__device__ __nv_bfloat16 g_qkvhi[(size_t)NTOK * QKVW];
__device__ __nv_bfloat16 g_qkvlo[(size_t)NTOK * QKVW];
__device__ __nv_bfloat16 g_ahi[(size_t)NTOK * DMODEL];
__device__ __nv_bfloat16 g_alo[(size_t)NTOK * DMODEL];

// ---------------------------------------------------------------------------
// Helpers
// ---------------------------------------------------------------------------
__device__ __forceinline__ uint32_t smem_u32(const void* p) {
    uint32_t a;
    asm("{ .reg .u64 t; cvta.to.shared.u64 t, %1; cvt.u32.u64 %0, t; }" : "=r"(a) : "l"(p));
    return a;
}
__device__ __forceinline__ void cp16(uint32_t dst, const void* src) {
    asm volatile("cp.async.cg.shared.global [%0], [%1], 16;" :: "r"(dst), "l"(src));
}
__device__ __forceinline__ void ldsm_x4(uint32_t* r, uint32_t addr) {
    asm volatile("ldmatrix.sync.aligned.m8n8.x4.shared.b16 {%0,%1,%2,%3}, [%4];"
                 : "=r"(r[0]), "=r"(r[1]), "=r"(r[2]), "=r"(r[3]) : "r"(addr));
}
__device__ __forceinline__ void ldsm_x4t(uint32_t* r, uint32_t addr) {
    asm volatile("ldmatrix.sync.aligned.m8n8.x4.trans.shared.b16 {%0,%1,%2,%3}, [%4];"
                 : "=r"(r[0]), "=r"(r[1]), "=r"(r[2]), "=r"(r[3]) : "r"(addr));
}
__device__ __forceinline__ void mma16816(float* d, const uint32_t* a, const uint32_t* b) {
    asm volatile("mma.sync.aligned.m16n8k16.row.col.f32.bf16.bf16.f32 "
                 "{%0,%1,%2,%3}, {%4,%5,%6,%7}, {%8,%9}, {%0,%1,%2,%3};"
                 : "+f"(d[0]), "+f"(d[1]), "+f"(d[2]), "+f"(d[3])
                 : "r"(a[0]), "r"(a[1]), "r"(a[2]), "r"(a[3]), "r"(b[0]), "r"(b[1]));
}
// split fp32 pair -> (hi u32 bf16x2, lo u32 bf16x2)
__device__ __forceinline__ uint32_t pack_hl(float f0, float f1, uint32_t& lo) {
    __nv_bfloat16 h0 = __float2bfloat16(f0), h1 = __float2bfloat16(f1);
    __nv_bfloat16 l0 = __float2bfloat16(f0 - __bfloat162float(h0));
    __nv_bfloat16 l1 = __float2bfloat16(f1 - __bfloat162float(h1));
    __nv_bfloat162 hp(h0, h1), lp(l0, l1);
    lo = *(uint32_t*)&lp;
    return *(uint32_t*)&hp;
}

// ---------------------------------------------------------------------------
// bf16 split HGEMM via mma.sync:
// C = Ahi*Bhi^T + Ahi*Blo^T + Alo*Bhi^T.  TERM-MAJOR MMA ordering: each of the
// 3 terms sweeps all 32 distinct accumulators before any acc is revisited
// (reuse distance 32 MMAs) to break the RAW stall chain.
// CTA 128x256, BK=32, 8 warps (warp tile 64x64), 3-stage cp.async pipeline.
// ---------------------------------------------------------------------------
#define ROWB   80
#define A_ROWS 128
#define B_ROWS 256
#define ABUF   (A_ROWS * ROWB)          // 10240
#define BBUF   (B_ROWS * ROWB)          // 20480
#define STAGEB (2 * ABUF + 2 * BBUF)    // 61440
#define NSTAGE 3
#define GSMEM  (NSTAGE * STAGEB)        // 184320 B

__global__ __launch_bounds__(256, 1) void gemm_mma_split(
    const __nv_bfloat16* __restrict__ Ahi, const __nv_bfloat16* __restrict__ Alo,
    const __nv_bfloat16* __restrict__ Bhi, const __nv_bfloat16* __restrict__ Blo,
    float* __restrict__ C, __nv_bfloat16* __restrict__ Chi, __nv_bfloat16* __restrict__ Clo,
    int K, int ldc)
{
    extern __shared__ char dynsm[];
    const uint32_t smb = smem_u32(dynsm);
    const int tid  = threadIdx.x;
    const int wid  = tid >> 5;
    const int lane = tid & 31;
    const int m0 = blockIdx.x * 128;
    const int n0 = blockIdx.y * 256;
    const int nch = K >> 5;

    auto load_stage = [&](int c, int st) {
        const uint32_t sb = smb + st * STAGEB;
#pragma unroll
        for (int i = 0; i < 2; i++) {
            int o = i * 256 + tid;
            int r = o >> 2, s = o & 3;
            size_t go = (size_t)(m0 + r) * K + c * 32 + s * 8;
            uint32_t so = r * ROWB + s * 16;
            cp16(sb + so,        Ahi + go);
            cp16(sb + ABUF + so, Alo + go);
        }
#pragma unroll
        for (int i = 0; i < 4; i++) {
            int o = i * 256 + tid;
            int r = o >> 2, s = o & 3;
            size_t go = (size_t)(n0 + r) * K + c * 32 + s * 8;
            uint32_t so = r * ROWB + s * 16;
            cp16(sb + 2 * ABUF + so,        Bhi + go);
            cp16(sb + 2 * ABUF + BBUF + so, Blo + go);
        }
        asm volatile("cp.async.commit_group;" ::: "memory");
    };

    float acc[4][8][4];
#pragma unroll
    for (int mt = 0; mt < 4; mt++)
#pragma unroll
        for (int nt = 0; nt < 8; nt++)
#pragma unroll
            for (int q = 0; q < 4; q++) acc[mt][nt][q] = 0.f;

    load_stage(0, 0);
    load_stage(1, 1);

    const int wm = (wid >> 2) * 64;            // 0 or 64
    const int wn = (wid & 3) * 64;             // 0,64,128,192
    const int arow = lane & 15, acolg = lane >> 4;
    const int brow = ((lane >> 4) << 3) + (lane & 7);
    const int bkof = ((lane >> 3) & 1) * 16;

    for (int c = 0; c < nch; c++) {
        if (c + 1 < nch) asm volatile("cp.async.wait_group 1;" ::: "memory");
        else             asm volatile("cp.async.wait_group 0;" ::: "memory");
        __syncthreads();
        if (c + 2 < nch) load_stage(c + 2, (c + 2) % NSTAGE);

        const uint32_t sb   = smb + (c % NSTAGE) * STAGEB;
        const uint32_t aHiB = sb;
        const uint32_t aLoB = sb + ABUF;
        const uint32_t bHiB = sb + 2 * ABUF;
        const uint32_t bLoB = sb + 2 * ABUF + BBUF;

#pragma unroll
        for (int ks = 0; ks < 2; ks++) {
            const int kb = ks * 32;
            uint32_t ah[4][4], al[4][4], bh[4][4], bl[4][4];
#pragma unroll
            for (int mt = 0; mt < 4; mt++) {
                uint32_t ao = (wm + mt * 16 + arow) * ROWB + kb + acolg * 16;
                ldsm_x4(ah[mt], aHiB + ao);
                ldsm_x4(al[mt], aLoB + ao);
            }
#pragma unroll
            for (int ng = 0; ng < 4; ng++) {
                uint32_t bo = (wn + ng * 16 + brow) * ROWB + kb + bkof;
                ldsm_x4(bh[ng], bHiB + bo);
                ldsm_x4(bl[ng], bLoB + bo);
            }
            // term hh: 32 distinct accumulators
#pragma unroll
            for (int mt = 0; mt < 4; mt++)
#pragma unroll
                for (int ng = 0; ng < 4; ng++) {
                    mma16816(acc[mt][2 * ng],     ah[mt], bh[ng]);
                    mma16816(acc[mt][2 * ng + 1], ah[mt], bh[ng] + 2);
                }
            // term hl
#pragma unroll
            for (int mt = 0; mt < 4; mt++)
#pragma unroll
                for (int ng = 0; ng < 4; ng++) {
                    mma16816(acc[mt][2 * ng],     ah[mt], bl[ng]);
                    mma16816(acc[mt][2 * ng + 1], ah[mt], bl[ng] + 2);
                }
            // term lh
#pragma unroll
            for (int mt = 0; mt < 4; mt++)
#pragma unroll
                for (int ng = 0; ng < 4; ng++) {
                    mma16816(acc[mt][2 * ng],     al[mt], bh[ng]);
                    mma16816(acc[mt][2 * ng + 1], al[mt], bh[ng] + 2);
                }
        }
    }

#pragma unroll
    for (int mt = 0; mt < 4; mt++) {
        int r0 = m0 + wm + mt * 16 + (lane >> 2);
#pragma unroll
        for (int nt = 0; nt < 8; nt++) {
            int cc = n0 + wn + nt * 8 + (lane & 3) * 2;
            if (Chi) {
                uint32_t lo0, lo1;
                uint32_t hi0 = pack_hl(acc[mt][nt][0], acc[mt][nt][1], lo0);
                uint32_t hi1 = pack_hl(acc[mt][nt][2], acc[mt][nt][3], lo1);
                *(uint32_t*)(Chi + (size_t)r0 * ldc + cc)       = hi0;
                *(uint32_t*)(Clo + (size_t)r0 * ldc + cc)       = lo0;
                *(uint32_t*)(Chi + (size_t)(r0 + 8) * ldc + cc) = hi1;
                *(uint32_t*)(Clo + (size_t)(r0 + 8) * ldc + cc) = lo1;
            } else {
                *(float2*)(C + (size_t)r0 * ldc + cc)       = make_float2(acc[mt][nt][0], acc[mt][nt][1]);
                *(float2*)(C + (size_t)(r0 + 8) * ldc + cc) = make_float2(acc[mt][nt][2], acc[mt][nt][3]);
            }
        }
    }
}

// ---------------------------------------------------------------------------
// fp32 -> bf16 hi/lo split (4 elems/thread)
// ---------------------------------------------------------------------------
__global__ void split_bf16(const float* __restrict__ src,
                           __nv_bfloat16* __restrict__ hi,
                           __nv_bfloat16* __restrict__ lo, int n)
{
    int i = (blockIdx.x * 256 + threadIdx.x) * 4;
    if (i >= n) return;
    float4 v = *(const float4*)(src + i);
    uint32_t l0, l1;
    uint32_t h0 = pack_hl(v.x, v.y, l0);
    uint32_t h1 = pack_hl(v.z, v.w, l1);
    *(uint2*)(hi + i) = make_uint2(h0, h1);
    *(uint2*)(lo + i) = make_uint2(l0, l1);
}

// ---------------------------------------------------------------------------
// RoPE on hi/lo representation, in place on q + k of g_qkvhi/g_qkvlo
// ---------------------------------------------------------------------------
__global__ void rope_hl(__nv_bfloat16* __restrict__ hi, __nv_bfloat16* __restrict__ lo,
                        const float* __restrict__ cosp, const float* __restrict__ sinp)
{
    int idx = blockIdx.x * 256 + threadIdx.x;
    if (idx >= NTOK * 40 * 64) return;
    int p  = idx & 63;
    int h2 = (idx >> 6) % 40;
    int t  = idx / (64 * 40);
    float c  = cosp[(size_t)t * 64 + p];
    float sn = sinp[(size_t)t * 64 + p];
    size_t base = (size_t)t * QKVW + (h2 < 32 ? h2 * HDIM : 4096 + (h2 - 32) * HDIM) + 2 * p;
    float t0 = __bfloat162float(hi[base])     + __bfloat162float(lo[base]);
    float t1 = __bfloat162float(hi[base + 1]) + __bfloat162float(lo[base + 1]);
    float r0 = t0 * c - t1 * sn;
    float r1 = t0 * sn + t1 * c;
    uint32_t lp;
    uint32_t hp = pack_hl(r0, r1, lp);
    *(uint32_t*)(hi + base) = hp;
    *(uint32_t*)(lo + base) = lp;
}

// ---------------------------------------------------------------------------
// Flash attention, tensor-core (bf16 3-term split), causal, GQA 4:1.
// Term-major MMA ordering in both S and PV phases (RAW stall mitigation).
// ---------------------------------------------------------------------------
#define FROW    272
#define FQLO    (128 * FROW)
#define FSTAGE0 (2 * 128 * FROW)
#define FSTAGESZ (4 * 64 * FROW)
#define FK_HI 0
#define FK_LO (64 * FROW)
#define FV_HI (2 * 64 * FROW)
#define FV_LO (3 * 64 * FROW)
#define FSMEM (FSTAGE0 + 2 * FSTAGESZ)   // 208896 B

__global__ __launch_bounds__(256, 1) void flash_mma(
    const __nv_bfloat16* __restrict__ qhi, const __nv_bfloat16* __restrict__ qlo,
    __nv_bfloat16* __restrict__ ohi_g, __nv_bfloat16* __restrict__ olo_g)
{
    extern __shared__ char fsm[];
    const uint32_t smb = smem_u32(fsm);
    const int qt = 15 - (int)blockIdx.x;
    const int h  = blockIdx.y;
    const int b  = blockIdx.z;
    const int kvh = h >> 2;
    const int tid = threadIdx.x, wid = tid >> 5, lane = tid & 31;
    const int nkt = 2 * qt + 2;

    const size_t tokQ = (size_t)b * SLEN + (size_t)qt * 128;
    const __nv_bfloat16* Qhg = qhi + tokQ * QKVW + h * HDIM;
    const __nv_bfloat16* Qlg = qlo + tokQ * QKVW + h * HDIM;
    const size_t kvbase = (size_t)b * SLEN * QKVW + kvh * HDIM;
    const __nv_bfloat16* Khg = qhi + kvbase + 4096;
    const __nv_bfloat16* Klg = qlo + kvbase + 4096;
    const __nv_bfloat16* Vhg = qhi + kvbase + 5120;
    const __nv_bfloat16* Vlg = qlo + kvbase + 5120;

    auto load_kv = [&](int kt, int buf) {
        const uint32_t sb = smb + FSTAGE0 + buf * FSTAGESZ;
#pragma unroll
        for (int i = 0; i < 4; i++) {
            int ch = tid + i * 256;
            int r = ch >> 4, s = ch & 15;
            size_t go = (size_t)(kt * 64 + r) * QKVW + s * 8;
            uint32_t so = r * FROW + s * 16;
            cp16(sb + FK_HI + so, Khg + go);
            cp16(sb + FK_LO + so, Klg + go);
            cp16(sb + FV_HI + so, Vhg + go);
            cp16(sb + FV_LO + so, Vlg + go);
        }
        asm volatile("cp.async.commit_group;" ::: "memory");
    };

#pragma unroll
    for (int i = 0; i < 8; i++) {
        int ch = tid + i * 256;
        int r = ch >> 4, s = ch & 15;
        size_t go = (size_t)r * QKVW + s * 8;
        uint32_t so = r * FROW + s * 16;
        cp16(smb + so,        Qhg + go);
        cp16(smb + FQLO + so, Qlg + go);
    }
    load_kv(0, 0);
    load_kv(1, 1);

    float o[16][4];
#pragma unroll
    for (int ct = 0; ct < 16; ct++)
#pragma unroll
        for (int q = 0; q < 4; q++) o[ct][q] = 0.f;
    float m0 = -1e30f, m1 = -1e30f, l0 = 0.f, l1 = 0.f;

    const uint32_t aAddr0 = smb + (wid * 16 + (lane & 15)) * FROW + (lane >> 4) * 16;
    const int brow = ((lane >> 4) << 3) + (lane & 7);
    const int bkof = ((lane >> 3) & 1) * 16;
    const int vrowl = ((lane >> 3) & 1) * 8 + (lane & 7);
    const int vcof = ((lane >> 4) << 3) * 2;

    for (int kt = 0; kt < nkt; kt++) {
        if (kt + 1 < nkt) asm volatile("cp.async.wait_group 1;" ::: "memory");
        else              asm volatile("cp.async.wait_group 0;" ::: "memory");
        __syncthreads();

        const uint32_t Kb = smb + FSTAGE0 + (kt & 1) * FSTAGESZ;

        float s[8][4];
#pragma unroll
        for (int nt = 0; nt < 8; nt++)
#pragma unroll
            for (int q = 0; q < 4; q++) s[nt][q] = 0.f;

#pragma unroll
        for (int ks = 0; ks < 8; ks++) {
            uint32_t ah[4], al[4], bh[4][4], bl[4][4];
            ldsm_x4(ah, aAddr0 + ks * 32);
            ldsm_x4(al, aAddr0 + FQLO + ks * 32);
#pragma unroll
            for (int np = 0; np < 4; np++) {
                uint32_t ba = Kb + (np * 16 + brow) * FROW + ks * 32 + bkof;
                ldsm_x4(bh[np], ba + FK_HI);
                ldsm_x4(bl[np], ba + FK_LO);
            }
            // term-major: 8 distinct accs per term
#pragma unroll
            for (int np = 0; np < 4; np++) {
                mma16816(s[2 * np],     ah, bh[np]);
                mma16816(s[2 * np + 1], ah, bh[np] + 2);
            }
#pragma unroll
            for (int np = 0; np < 4; np++) {
                mma16816(s[2 * np],     ah, bl[np]);
                mma16816(s[2 * np + 1], ah, bl[np] + 2);
            }
#pragma unroll
            for (int np = 0; np < 4; np++) {
                mma16816(s[2 * np],     al, bh[np]);
                mma16816(s[2 * np + 1], al, bh[np] + 2);
            }
        }

        const bool need_mask = (kt >= 2 * qt);
        const int rg0 = qt * 128 + wid * 16 + (lane >> 2);
#pragma unroll
        for (int nt = 0; nt < 8; nt++) {
#pragma unroll
            for (int q = 0; q < 4; q++) {
                float v = s[nt][q] * ATT_SCALE;
                if (need_mask) {
                    int col = kt * 64 + nt * 8 + (lane & 3) * 2 + (q & 1);
                    int row = rg0 + ((q >> 1) << 3);
                    if (col > row) v = -1e30f;
                }
                s[nt][q] = v;
            }
        }
        float mx0 = -1e30f, mx1 = -1e30f;
#pragma unroll
        for (int nt = 0; nt < 8; nt++) {
            mx0 = fmaxf(mx0, fmaxf(s[nt][0], s[nt][1]));
            mx1 = fmaxf(mx1, fmaxf(s[nt][2], s[nt][3]));
        }
        mx0 = fmaxf(mx0, __shfl_xor_sync(0xffffffffu, mx0, 1));
        mx0 = fmaxf(mx0, __shfl_xor_sync(0xffffffffu, mx0, 2));
        mx1 = fmaxf(mx1, __shfl_xor_sync(0xffffffffu, mx1, 1));
        mx1 = fmaxf(mx1, __shfl_xor_sync(0xffffffffu, mx1, 2));

        float mn0 = fmaxf(m0, mx0), mn1 = fmaxf(m1, mx1);
        float al0 = __expf(m0 - mn0), al1 = __expf(m1 - mn1);
        m0 = mn0; m1 = mn1;
        float rs0 = 0.f, rs1 = 0.f;
#pragma unroll
        for (int nt = 0; nt < 8; nt++) {
            float p0 = __expf(s[nt][0] - mn0);
            float p1 = __expf(s[nt][1] - mn0);
            float p2 = __expf(s[nt][2] - mn1);
            float p3 = __expf(s[nt][3] - mn1);
            s[nt][0] = p0; s[nt][1] = p1; s[nt][2] = p2; s[nt][3] = p3;
            rs0 += p0 + p1; rs1 += p2 + p3;
        }
        rs0 += __shfl_xor_sync(0xffffffffu, rs0, 1);
        rs0 += __shfl_xor_sync(0xffffffffu, rs0, 2);
        rs1 += __shfl_xor_sync(0xffffffffu, rs1, 1);
        rs1 += __shfl_xor_sync(0xffffffffu, rs1, 2);
        l0 = l0 * al0 + rs0;
        l1 = l1 * al1 + rs1;
#pragma unroll
        for (int ct = 0; ct < 16; ct++) {
            o[ct][0] *= al0; o[ct][1] *= al0;
            o[ct][2] *= al1; o[ct][3] *= al1;
        }

        // ---- PV: per kj, load all 16 V frags, then term-major across cp2 ----
#pragma unroll
        for (int kj = 0; kj < 4; kj++) {
            uint32_t ph[4], pl[4];
            ph[0] = pack_hl(s[2 * kj][0],     s[2 * kj][1],     pl[0]);
            ph[1] = pack_hl(s[2 * kj][2],     s[2 * kj][3],     pl[1]);
            ph[2] = pack_hl(s[2 * kj + 1][0], s[2 * kj + 1][1], pl[2]);
            ph[3] = pack_hl(s[2 * kj + 1][2], s[2 * kj + 1][3], pl[3]);
            uint32_t vbase = Kb + (kj * 16 + vrowl) * FROW + vcof;
            uint32_t vh[8][4], vl[8][4];
#pragma unroll
            for (int cp2 = 0; cp2 < 8; cp2++) {
                uint32_t va = vbase + cp2 * 32;
                ldsm_x4t(vh[cp2], va + FV_HI);
                ldsm_x4t(vl[cp2], va + FV_LO);
            }
#pragma unroll
            for (int cp2 = 0; cp2 < 8; cp2++) {
                mma16816(o[2 * cp2],     ph, vh[cp2]);
                mma16816(o[2 * cp2 + 1], ph, vh[cp2] + 2);
            }
#pragma unroll
            for (int cp2 = 0; cp2 < 8; cp2++) {
                mma16816(o[2 * cp2],     pl, vh[cp2]);
                mma16816(o[2 * cp2 + 1], pl, vh[cp2] + 2);
            }
#pragma unroll
            for (int cp2 = 0; cp2 < 8; cp2++) {
                mma16816(o[2 * cp2],     ph, vl[cp2]);
                mma16816(o[2 * cp2 + 1], ph, vl[cp2] + 2);
            }
        }

        __syncthreads();
        if (kt + 2 < nkt) load_kv(kt + 2, kt & 1);
    }

    float inv0 = 1.0f / l0, inv1 = 1.0f / l1;
    size_t trow0 = (size_t)b * SLEN + qt * 128 + wid * 16 + (lane >> 2);
    int colb = h * HDIM + (lane & 3) * 2;
#pragma unroll
    for (int ct = 0; ct < 16; ct++) {
        int col = colb + ct * 8;
        uint32_t lo0, lo1;
        uint32_t hi0 = pack_hl(o[ct][0] * inv0, o[ct][1] * inv0, lo0);
        uint32_t hi1 = pack_hl(o[ct][2] * inv1, o[ct][3] * inv1, lo1);
        *(uint32_t*)(ohi_g + trow0 * DMODEL + col)       = hi0;
        *(uint32_t*)(olo_g + trow0 * DMODEL + col)       = lo0;
        *(uint32_t*)(ohi_g + (trow0 + 8) * DMODEL + col) = hi1;
        *(uint32_t*)(olo_g + (trow0 + 8) * DMODEL + col) = lo1;
    }
}

// ---------------------------------------------------------------------------
// Launch. inputs: 0=x 1=mask(all-true) 2=cos 3=sin 4=wq 5=wk 6=wv 7=wo
// ---------------------------------------------------------------------------
extern "C" void kernel_launch(void* const* d_in, const int* in_sizes, int n_in,
                              void* d_out, int out_size)
{
    const float* x    = (const float*)d_in[0];
    const float* cosp = (const float*)d_in[2];
    const float* sinp = (const float*)d_in[3];
    const float* wq   = (const float*)d_in[4];
    const float* wk   = (const float*)d_in[5];
    const float* wv   = (const float*)d_in[6];
    const float* wo   = (const float*)d_in[7];
    float* outp = (float*)d_out;

    __nv_bfloat16 *xhi, *xlo, *whi, *wlo, *wohi, *wolo, *qkvhi, *qkvlo, *ahi, *alo;
    cudaGetSymbolAddress((void**)&xhi,   g_xhi);
    cudaGetSymbolAddress((void**)&xlo,   g_xlo);
    cudaGetSymbolAddress((void**)&whi,   g_whi);
    cudaGetSymbolAddress((void**)&wlo,   g_wlo);
    cudaGetSymbolAddress((void**)&wohi,  g_wohi);
    cudaGetSymbolAddress((void**)&wolo,  g_wolo);
    cudaGetSymbolAddress((void**)&qkvhi, g_qkvhi);
    cudaGetSymbolAddress((void**)&qkvlo, g_qkvlo);
    cudaGetSymbolAddress((void**)&ahi,   g_ahi);
    cudaGetSymbolAddress((void**)&alo,   g_alo);

    cudaFuncSetAttribute(gemm_mma_split, cudaFuncAttributeMaxDynamicSharedMemorySize, GSMEM);
    cudaFuncSetAttribute(flash_mma, cudaFuncAttributeMaxDynamicSharedMemorySize, FSMEM);

    const int NX = NTOK * DMODEL;
    const int NW = DMODEL * DMODEL;
    const int NK = NKVH * HDIM * DMODEL;
    split_bf16<<<NX / 1024, 256>>>(x,  xhi,  xlo,  NX);
    split_bf16<<<NW / 1024, 256>>>(wq, whi,  wlo,  NW);
    split_bf16<<<NK / 1024, 256>>>(wk, whi + (size_t)4096 * DMODEL, wlo + (size_t)4096 * DMODEL, NK);
    split_bf16<<<NK / 1024, 256>>>(wv, whi + (size_t)5120 * DMODEL, wlo + (size_t)5120 * DMODEL, NK);
    split_bf16<<<NW / 1024, 256>>>(wo, wohi, wolo, NW);

    // Fused QKV projection -> hi/lo bf16 directly
    gemm_mma_split<<<dim3(NTOK / 128, QKVW / 256), 256, GSMEM>>>(
        xhi, xlo, whi, wlo, nullptr, qkvhi, qkvlo, DMODEL, QKVW);

    // RoPE in hi/lo domain on q and k
    rope_hl<<<(NTOK * 40 * 64) / 256, 256>>>(qkvhi, qkvlo, cosp, sinp);

    // Tensor-core causal GQA attention -> ahi/alo
    flash_mma<<<dim3(SLEN / 128, NHEAD, BATCH), 256, FSMEM>>>(qkvhi, qkvlo, ahi, alo);

    // Output projection -> fp32 d_out
    gemm_mma_split<<<dim3(NTOK / 128, DMODEL / 256), 256, GSMEM>>>(
        ahi, alo, wohi, wolo, outp, nullptr, nullptr, DMODEL, DMODEL);
}

// round 14
// speedup vs baseline: 2.2633x; 1.0355x over previous
#include <cuda_runtime.h>
#include <cuda_bf16.h>
#include <cstdint>

// Problem constants
#define BATCH 2
#define SLEN  2048
#define DMODEL 4096
#define NHEAD 32
#define NKVH  8
#define HDIM  128
#define NTOK  (BATCH*SLEN)          // 4096
#define QKVW  6144                  // 4096 q + 1024 k + 1024 v
#define ATT_SCALE 0.08838834764831845f

// ---------------------------------------------------------------------------
// Scratch (allocation-free rule: __device__ globals)
// ---------------------------------------------------------------------------
__device__ __nv_bfloat16 g_xhi[(size_t)NTOK * DMODEL];
__device__ __nv_bfloat16 g_xlo[(size_t)NTOK * DMODEL];
__device__ __nv_bfloat16 g_whi[(size_t)QKVW * DMODEL];   // fused wq|wk|wv rows
__device__ __nv_bfloat16 g_wlo[(size_t)QKVW * DMODEL];
__device__ __nv_bfloat16 g_wohi[(size_t)DMODEL * DMODEL];
__device__ __nv_bfloat16 g_wolo[(size_t)DMODEL * DMODEL];
__device__ __nv_bfloat16 g_qkvhi[(size_t)NTOK * QKVW];
__device__ __nv_bfloat16 g_qkvlo[(size_t)NTOK * QKVW];
__device__ __nv_bfloat16 g_ahi[(size_t)NTOK * DMODEL];
__device__ __nv_bfloat16 g_alo[(size_t)NTOK * DMODEL];

// ---------------------------------------------------------------------------
// Helpers
// ---------------------------------------------------------------------------
__device__ __forceinline__ uint32_t smem_u32(const void* p) {
    uint32_t a;
    asm("{ .reg .u64 t; cvta.to.shared.u64 t, %1; cvt.u32.u64 %0, t; }" : "=r"(a) : "l"(p));
    return a;
}
__device__ __forceinline__ void cp16(uint32_t dst, const void* src) {
    asm volatile("cp.async.cg.shared.global [%0], [%1], 16;" :: "r"(dst), "l"(src));
}
__device__ __forceinline__ void ldsm_x4(uint32_t* r, uint32_t addr) {
    asm volatile("ldmatrix.sync.aligned.m8n8.x4.shared.b16 {%0,%1,%2,%3}, [%4];"
                 : "=r"(r[0]), "=r"(r[1]), "=r"(r[2]), "=r"(r[3]) : "r"(addr));
}
__device__ __forceinline__ void ldsm_x4t(uint32_t* r, uint32_t addr) {
    asm volatile("ldmatrix.sync.aligned.m8n8.x4.trans.shared.b16 {%0,%1,%2,%3}, [%4];"
                 : "=r"(r[0]), "=r"(r[1]), "=r"(r[2]), "=r"(r[3]) : "r"(addr));
}
__device__ __forceinline__ void mma16816(float* d, const uint32_t* a, const uint32_t* b) {
    asm volatile("mma.sync.aligned.m16n8k16.row.col.f32.bf16.bf16.f32 "
                 "{%0,%1,%2,%3}, {%4,%5,%6,%7}, {%8,%9}, {%0,%1,%2,%3};"
                 : "+f"(d[0]), "+f"(d[1]), "+f"(d[2]), "+f"(d[3])
                 : "r"(a[0]), "r"(a[1]), "r"(a[2]), "r"(a[3]), "r"(b[0]), "r"(b[1]));
}
// split fp32 pair -> (hi u32 bf16x2, lo u32 bf16x2)
__device__ __forceinline__ uint32_t pack_hl(float f0, float f1, uint32_t& lo) {
    __nv_bfloat16 h0 = __float2bfloat16(f0), h1 = __float2bfloat16(f1);
    __nv_bfloat16 l0 = __float2bfloat16(f0 - __bfloat162float(h0));
    __nv_bfloat16 l1 = __float2bfloat16(f1 - __bfloat162float(h1));
    __nv_bfloat162 hp(h0, h1), lp(l0, l1);
    lo = *(uint32_t*)&lp;
    return *(uint32_t*)&hp;
}

// ---------------------------------------------------------------------------
// bf16 split HGEMM via mma.sync, templated warp microtile:
//   C = Ahi*Bhi^T + Ahi*Blo^T + Alo*Bhi^T
// Warp grid 2(m) x 4(n). Warp tile (MT*16) x (NG*16).
// CTA tile (2*MT*16) x (4*NG*16). BK=32, 3-stage cp.async pipeline.
// Optional fused interleaved RoPE in the hi/lo epilogue (QKV path).
// ---------------------------------------------------------------------------
#define ROWB   80
#define NSTAGE 3

template<int MT, int NG>
__global__ __launch_bounds__(256, 1) void gemm_mma_split(
    const __nv_bfloat16* __restrict__ Ahi, const __nv_bfloat16* __restrict__ Alo,
    const __nv_bfloat16* __restrict__ Bhi, const __nv_bfloat16* __restrict__ Blo,
    float* __restrict__ C, __nv_bfloat16* __restrict__ Chi, __nv_bfloat16* __restrict__ Clo,
    const float* __restrict__ cosp, const float* __restrict__ sinp,
    int K, int ldc)
{
    constexpr int M_CTA = 2 * MT * 16;
    constexpr int N_CTA = 4 * NG * 16;
    constexpr int ABUF  = M_CTA * ROWB;
    constexpr int BBUF  = N_CTA * ROWB;
    constexpr int STAGEB = 2 * ABUF + 2 * BBUF;

    extern __shared__ char dynsm[];
    const uint32_t smb = smem_u32(dynsm);
    const int tid  = threadIdx.x;
    const int wid  = tid >> 5;
    const int lane = tid & 31;
    const int m0 = blockIdx.x * M_CTA;
    const int n0 = blockIdx.y * N_CTA;
    const int nch = K >> 5;

    auto load_stage = [&](int c, int st) {
        const uint32_t sb = smb + st * STAGEB;
#pragma unroll
        for (int i = 0; i < M_CTA / 64; i++) {
            int o = i * 256 + tid;
            int r = o >> 2, s = o & 3;
            size_t go = (size_t)(m0 + r) * K + c * 32 + s * 8;
            uint32_t so = r * ROWB + s * 16;
            cp16(sb + so,        Ahi + go);
            cp16(sb + ABUF + so, Alo + go);
        }
#pragma unroll
        for (int i = 0; i < N_CTA / 64; i++) {
            int o = i * 256 + tid;
            int r = o >> 2, s = o & 3;
            size_t go = (size_t)(n0 + r) * K + c * 32 + s * 8;
            uint32_t so = r * ROWB + s * 16;
            cp16(sb + 2 * ABUF + so,        Bhi + go);
            cp16(sb + 2 * ABUF + BBUF + so, Blo + go);
        }
        asm volatile("cp.async.commit_group;" ::: "memory");
    };

    float acc[MT][2 * NG][4];
#pragma unroll
    for (int mt = 0; mt < MT; mt++)
#pragma unroll
        for (int nt = 0; nt < 2 * NG; nt++)
#pragma unroll
            for (int q = 0; q < 4; q++) acc[mt][nt][q] = 0.f;

    load_stage(0, 0);
    load_stage(1, 1);

    const int wm = (wid >> 2) * MT * 16;
    const int wn = (wid & 3) * NG * 16;
    const int arow = lane & 15, acolg = lane >> 4;
    const int brow = ((lane >> 4) << 3) + (lane & 7);
    const int bkof = ((lane >> 3) & 1) * 16;

    for (int c = 0; c < nch; c++) {
        if (c + 1 < nch) asm volatile("cp.async.wait_group 1;" ::: "memory");
        else             asm volatile("cp.async.wait_group 0;" ::: "memory");
        __syncthreads();
        if (c + 2 < nch) load_stage(c + 2, (c + 2) % NSTAGE);

        const uint32_t sb   = smb + (c % NSTAGE) * STAGEB;
        const uint32_t aHiB = sb;
        const uint32_t aLoB = sb + ABUF;
        const uint32_t bHiB = sb + 2 * ABUF;
        const uint32_t bLoB = sb + 2 * ABUF + BBUF;

#pragma unroll
        for (int ks = 0; ks < 2; ks++) {
            const int kb = ks * 32;
            uint32_t ah[MT][4], al[MT][4], bh[NG][4], bl[NG][4];
#pragma unroll
            for (int mt = 0; mt < MT; mt++) {
                uint32_t ao = (wm + mt * 16 + arow) * ROWB + kb + acolg * 16;
                ldsm_x4(ah[mt], aHiB + ao);
                ldsm_x4(al[mt], aLoB + ao);
            }
#pragma unroll
            for (int ng = 0; ng < NG; ng++) {
                uint32_t bo = (wn + ng * 16 + brow) * ROWB + kb + bkof;
                ldsm_x4(bh[ng], bHiB + bo);
                ldsm_x4(bl[ng], bLoB + bo);
            }
#pragma unroll
            for (int mt = 0; mt < MT; mt++)
#pragma unroll
                for (int ng = 0; ng < NG; ng++) {
                    mma16816(acc[mt][2 * ng],     ah[mt], bh[ng]);
                    mma16816(acc[mt][2 * ng + 1], ah[mt], bh[ng] + 2);
                }
#pragma unroll
            for (int mt = 0; mt < MT; mt++)
#pragma unroll
                for (int ng = 0; ng < NG; ng++) {
                    mma16816(acc[mt][2 * ng],     ah[mt], bl[ng]);
                    mma16816(acc[mt][2 * ng + 1], ah[mt], bl[ng] + 2);
                }
#pragma unroll
            for (int mt = 0; mt < MT; mt++)
#pragma unroll
                for (int ng = 0; ng < NG; ng++) {
                    mma16816(acc[mt][2 * ng],     al[mt], bh[ng]);
                    mma16816(acc[mt][2 * ng + 1], al[mt], bh[ng] + 2);
                }
        }
    }

#pragma unroll
    for (int mt = 0; mt < MT; mt++) {
        int r0 = m0 + wm + mt * 16 + (lane >> 2);
#pragma unroll
        for (int nt = 0; nt < 2 * NG; nt++) {
            int cc = n0 + wn + nt * 8 + (lane & 3) * 2;
            float v[4] = { acc[mt][nt][0], acc[mt][nt][1], acc[mt][nt][2], acc[mt][nt][3] };
            if (Chi) {
                // fused interleaved RoPE on q (cols<4096) and k (4096..5119).
                // v[0],v[1] = pair (2p,2p+1) at token r0; v[2],v[3] same at r0+8.
                if (cc < 5120) {
                    int p = (cc & 127) >> 1;
                    float c0 = cosp[(size_t)r0 * 64 + p];
                    float s0 = sinp[(size_t)r0 * 64 + p];
                    float c1 = cosp[(size_t)(r0 + 8) * 64 + p];
                    float s1 = sinp[(size_t)(r0 + 8) * 64 + p];
                    float t0 = v[0], t1 = v[1];
                    v[0] = t0 * c0 - t1 * s0;
                    v[1] = t0 * s0 + t1 * c0;
                    t0 = v[2]; t1 = v[3];
                    v[2] = t0 * c1 - t1 * s1;
                    v[3] = t0 * s1 + t1 * c1;
                }
                uint32_t lo0, lo1;
                uint32_t hi0 = pack_hl(v[0], v[1], lo0);
                uint32_t hi1 = pack_hl(v[2], v[3], lo1);
                *(uint32_t*)(Chi + (size_t)r0 * ldc + cc)       = hi0;
                *(uint32_t*)(Clo + (size_t)r0 * ldc + cc)       = lo0;
                *(uint32_t*)(Chi + (size_t)(r0 + 8) * ldc + cc) = hi1;
                *(uint32_t*)(Clo + (size_t)(r0 + 8) * ldc + cc) = lo1;
            } else {
                *(float2*)(C + (size_t)r0 * ldc + cc)       = make_float2(v[0], v[1]);
                *(float2*)(C + (size_t)(r0 + 8) * ldc + cc) = make_float2(v[2], v[3]);
            }
        }
    }
}

// QKV: 128x192 tiles (MT=4, NG=3) -> grid (32, 32) = 1024 tiles
// OUT: 64x256 tiles  (MT=2, NG=4) -> grid (64, 16) = 1024 tiles
#define GSMEM_QKV (NSTAGE * (2 * 128 * ROWB + 2 * 192 * ROWB))   // 153600
#define GSMEM_OUT (NSTAGE * (2 * 64 * ROWB + 2 * 256 * ROWB))    // 153600

// ---------------------------------------------------------------------------
// fp32 -> bf16 hi/lo split (4 elems/thread)
// ---------------------------------------------------------------------------
__global__ void split_bf16(const float* __restrict__ src,
                           __nv_bfloat16* __restrict__ hi,
                           __nv_bfloat16* __restrict__ lo, int n)
{
    int i = (blockIdx.x * 256 + threadIdx.x) * 4;
    if (i >= n) return;
    float4 v = *(const float4*)(src + i);
    uint32_t l0, l1;
    uint32_t h0 = pack_hl(v.x, v.y, l0);
    uint32_t h1 = pack_hl(v.z, v.w, l1);
    *(uint2*)(hi + i) = make_uint2(h0, h1);
    *(uint2*)(lo + i) = make_uint2(l0, l1);
}

// ---------------------------------------------------------------------------
// Flash attention, tensor-core (bf16 3-term split), causal, GQA 4:1.
// (unchanged from R11 — known correct)
// ---------------------------------------------------------------------------
#define FROW    272
#define FQLO    (128 * FROW)
#define FSTAGE0 (2 * 128 * FROW)
#define FSTAGESZ (4 * 64 * FROW)
#define FK_HI 0
#define FK_LO (64 * FROW)
#define FV_HI (2 * 64 * FROW)
#define FV_LO (3 * 64 * FROW)
#define FSMEM (FSTAGE0 + 2 * FSTAGESZ)   // 208896 B

__global__ __launch_bounds__(256, 1) void flash_mma(
    const __nv_bfloat16* __restrict__ qhi, const __nv_bfloat16* __restrict__ qlo,
    __nv_bfloat16* __restrict__ ohi_g, __nv_bfloat16* __restrict__ olo_g)
{
    extern __shared__ char fsm[];
    const uint32_t smb = smem_u32(fsm);
    const int qt = 15 - (int)blockIdx.x;
    const int h  = blockIdx.y;
    const int b  = blockIdx.z;
    const int kvh = h >> 2;
    const int tid = threadIdx.x, wid = tid >> 5, lane = tid & 31;
    const int nkt = 2 * qt + 2;

    const size_t tokQ = (size_t)b * SLEN + (size_t)qt * 128;
    const __nv_bfloat16* Qhg = qhi + tokQ * QKVW + h * HDIM;
    const __nv_bfloat16* Qlg = qlo + tokQ * QKVW + h * HDIM;
    const size_t kvbase = (size_t)b * SLEN * QKVW + kvh * HDIM;
    const __nv_bfloat16* Khg = qhi + kvbase + 4096;
    const __nv_bfloat16* Klg = qlo + kvbase + 4096;
    const __nv_bfloat16* Vhg = qhi + kvbase + 5120;
    const __nv_bfloat16* Vlg = qlo + kvbase + 5120;

    auto load_kv = [&](int kt, int buf) {
        const uint32_t sb = smb + FSTAGE0 + buf * FSTAGESZ;
#pragma unroll
        for (int i = 0; i < 4; i++) {
            int ch = tid + i * 256;
            int r = ch >> 4, s = ch & 15;
            size_t go = (size_t)(kt * 64 + r) * QKVW + s * 8;
            uint32_t so = r * FROW + s * 16;
            cp16(sb + FK_HI + so, Khg + go);
            cp16(sb + FK_LO + so, Klg + go);
            cp16(sb + FV_HI + so, Vhg + go);
            cp16(sb + FV_LO + so, Vlg + go);
        }
        asm volatile("cp.async.commit_group;" ::: "memory");
    };

#pragma unroll
    for (int i = 0; i < 8; i++) {
        int ch = tid + i * 256;
        int r = ch >> 4, s = ch & 15;
        size_t go = (size_t)r * QKVW + s * 8;
        uint32_t so = r * FROW + s * 16;
        cp16(smb + so,        Qhg + go);
        cp16(smb + FQLO + so, Qlg + go);
    }
    load_kv(0, 0);
    load_kv(1, 1);

    float o[16][4];
#pragma unroll
    for (int ct = 0; ct < 16; ct++)
#pragma unroll
        for (int q = 0; q < 4; q++) o[ct][q] = 0.f;
    float m0 = -1e30f, m1 = -1e30f, l0 = 0.f, l1 = 0.f;

    const uint32_t aAddr0 = smb + (wid * 16 + (lane & 15)) * FROW + (lane >> 4) * 16;
    const int brow = ((lane >> 4) << 3) + (lane & 7);
    const int bkof = ((lane >> 3) & 1) * 16;
    const int vrowl = ((lane >> 3) & 1) * 8 + (lane & 7);
    const int vcof = ((lane >> 4) << 3) * 2;

    for (int kt = 0; kt < nkt; kt++) {
        if (kt + 1 < nkt) asm volatile("cp.async.wait_group 1;" ::: "memory");
        else              asm volatile("cp.async.wait_group 0;" ::: "memory");
        __syncthreads();

        const uint32_t Kb = smb + FSTAGE0 + (kt & 1) * FSTAGESZ;

        float s[8][4];
#pragma unroll
        for (int nt = 0; nt < 8; nt++)
#pragma unroll
            for (int q = 0; q < 4; q++) s[nt][q] = 0.f;

#pragma unroll
        for (int ks = 0; ks < 8; ks++) {
            uint32_t ah[4], al[4], bh[4][4], bl[4][4];
            ldsm_x4(ah, aAddr0 + ks * 32);
            ldsm_x4(al, aAddr0 + FQLO + ks * 32);
#pragma unroll
            for (int np = 0; np < 4; np++) {
                uint32_t ba = Kb + (np * 16 + brow) * FROW + ks * 32 + bkof;
                ldsm_x4(bh[np], ba + FK_HI);
                ldsm_x4(bl[np], ba + FK_LO);
            }
#pragma unroll
            for (int np = 0; np < 4; np++) {
                mma16816(s[2 * np],     ah, bh[np]);
                mma16816(s[2 * np + 1], ah, bh[np] + 2);
            }
#pragma unroll
            for (int np = 0; np < 4; np++) {
                mma16816(s[2 * np],     ah, bl[np]);
                mma16816(s[2 * np + 1], ah, bl[np] + 2);
            }
#pragma unroll
            for (int np = 0; np < 4; np++) {
                mma16816(s[2 * np],     al, bh[np]);
                mma16816(s[2 * np + 1], al, bh[np] + 2);
            }
        }

        const bool need_mask = (kt >= 2 * qt);
        const int rg0 = qt * 128 + wid * 16 + (lane >> 2);
#pragma unroll
        for (int nt = 0; nt < 8; nt++) {
#pragma unroll
            for (int q = 0; q < 4; q++) {
                float v = s[nt][q] * ATT_SCALE;
                if (need_mask) {
                    int col = kt * 64 + nt * 8 + (lane & 3) * 2 + (q & 1);
                    int row = rg0 + ((q >> 1) << 3);
                    if (col > row) v = -1e30f;
                }
                s[nt][q] = v;
            }
        }
        float mx0 = -1e30f, mx1 = -1e30f;
#pragma unroll
        for (int nt = 0; nt < 8; nt++) {
            mx0 = fmaxf(mx0, fmaxf(s[nt][0], s[nt][1]));
            mx1 = fmaxf(mx1, fmaxf(s[nt][2], s[nt][3]));
        }
        mx0 = fmaxf(mx0, __shfl_xor_sync(0xffffffffu, mx0, 1));
        mx0 = fmaxf(mx0, __shfl_xor_sync(0xffffffffu, mx0, 2));
        mx1 = fmaxf(mx1, __shfl_xor_sync(0xffffffffu, mx1, 1));
        mx1 = fmaxf(mx1, __shfl_xor_sync(0xffffffffu, mx1, 2));

        float mn0 = fmaxf(m0, mx0), mn1 = fmaxf(m1, mx1);
        float al0 = __expf(m0 - mn0), al1 = __expf(m1 - mn1);
        m0 = mn0; m1 = mn1;
        float rs0 = 0.f, rs1 = 0.f;
#pragma unroll
        for (int nt = 0; nt < 8; nt++) {
            float p0 = __expf(s[nt][0] - mn0);
            float p1 = __expf(s[nt][1] - mn0);
            float p2 = __expf(s[nt][2] - mn1);
            float p3 = __expf(s[nt][3] - mn1);
            s[nt][0] = p0; s[nt][1] = p1; s[nt][2] = p2; s[nt][3] = p3;
            rs0 += p0 + p1; rs1 += p2 + p3;
        }
        rs0 += __shfl_xor_sync(0xffffffffu, rs0, 1);
        rs0 += __shfl_xor_sync(0xffffffffu, rs0, 2);
        rs1 += __shfl_xor_sync(0xffffffffu, rs1, 1);
        rs1 += __shfl_xor_sync(0xffffffffu, rs1, 2);
        l0 = l0 * al0 + rs0;
        l1 = l1 * al1 + rs1;
#pragma unroll
        for (int ct = 0; ct < 16; ct++) {
            o[ct][0] *= al0; o[ct][1] *= al0;
            o[ct][2] *= al1; o[ct][3] *= al1;
        }

#pragma unroll
        for (int kj = 0; kj < 4; kj++) {
            uint32_t ph[4], pl[4];
            ph[0] = pack_hl(s[2 * kj][0],     s[2 * kj][1],     pl[0]);
            ph[1] = pack_hl(s[2 * kj][2],     s[2 * kj][3],     pl[1]);
            ph[2] = pack_hl(s[2 * kj + 1][0], s[2 * kj + 1][1], pl[2]);
            ph[3] = pack_hl(s[2 * kj + 1][2], s[2 * kj + 1][3], pl[3]);
            uint32_t vbase = Kb + (kj * 16 + vrowl) * FROW + vcof;
            uint32_t vh[8][4], vl[8][4];
#pragma unroll
            for (int cp2 = 0; cp2 < 8; cp2++) {
                uint32_t va = vbase + cp2 * 32;
                ldsm_x4t(vh[cp2], va + FV_HI);
                ldsm_x4t(vl[cp2], va + FV_LO);
            }
#pragma unroll
            for (int cp2 = 0; cp2 < 8; cp2++) {
                mma16816(o[2 * cp2],     ph, vh[cp2]);
                mma16816(o[2 * cp2 + 1], ph, vh[cp2] + 2);
            }
#pragma unroll
            for (int cp2 = 0; cp2 < 8; cp2++) {
                mma16816(o[2 * cp2],     pl, vh[cp2]);
                mma16816(o[2 * cp2 + 1], pl, vh[cp2] + 2);
            }
#pragma unroll
            for (int cp2 = 0; cp2 < 8; cp2++) {
                mma16816(o[2 * cp2],     ph, vl[cp2]);
                mma16816(o[2 * cp2 + 1], ph, vl[cp2] + 2);
            }
        }

        __syncthreads();
        if (kt + 2 < nkt) load_kv(kt + 2, kt & 1);
    }

    float inv0 = 1.0f / l0, inv1 = 1.0f / l1;
    size_t trow0 = (size_t)b * SLEN + qt * 128 + wid * 16 + (lane >> 2);
    int colb = h * HDIM + (lane & 3) * 2;
#pragma unroll
    for (int ct = 0; ct < 16; ct++) {
        int col = colb + ct * 8;
        uint32_t lo0, lo1;
        uint32_t hi0 = pack_hl(o[ct][0] * inv0, o[ct][1] * inv0, lo0);
        uint32_t hi1 = pack_hl(o[ct][2] * inv1, o[ct][3] * inv1, lo1);
        *(uint32_t*)(ohi_g + trow0 * DMODEL + col)       = hi0;
        *(uint32_t*)(olo_g + trow0 * DMODEL + col)       = lo0;
        *(uint32_t*)(ohi_g + (trow0 + 8) * DMODEL + col) = hi1;
        *(uint32_t*)(olo_g + (trow0 + 8) * DMODEL + col) = lo1;
    }
}

// ---------------------------------------------------------------------------
// Launch. inputs: 0=x 1=mask(all-true) 2=cos 3=sin 4=wq 5=wk 6=wv 7=wo
// ---------------------------------------------------------------------------
extern "C" void kernel_launch(void* const* d_in, const int* in_sizes, int n_in,
                              void* d_out, int out_size)
{
    const float* x    = (const float*)d_in[0];
    const float* cosp = (const float*)d_in[2];
    const float* sinp = (const float*)d_in[3];
    const float* wq   = (const float*)d_in[4];
    const float* wk   = (const float*)d_in[5];
    const float* wv   = (const float*)d_in[6];
    const float* wo   = (const float*)d_in[7];
    float* outp = (float*)d_out;

    __nv_bfloat16 *xhi, *xlo, *whi, *wlo, *wohi, *wolo, *qkvhi, *qkvlo, *ahi, *alo;
    cudaGetSymbolAddress((void**)&xhi,   g_xhi);
    cudaGetSymbolAddress((void**)&xlo,   g_xlo);
    cudaGetSymbolAddress((void**)&whi,   g_whi);
    cudaGetSymbolAddress((void**)&wlo,   g_wlo);
    cudaGetSymbolAddress((void**)&wohi,  g_wohi);
    cudaGetSymbolAddress((void**)&wolo,  g_wolo);
    cudaGetSymbolAddress((void**)&qkvhi, g_qkvhi);
    cudaGetSymbolAddress((void**)&qkvlo, g_qkvlo);
    cudaGetSymbolAddress((void**)&ahi,   g_ahi);
    cudaGetSymbolAddress((void**)&alo,   g_alo);

    cudaFuncSetAttribute(gemm_mma_split<4, 3>, cudaFuncAttributeMaxDynamicSharedMemorySize, GSMEM_QKV);
    cudaFuncSetAttribute(gemm_mma_split<2, 4>, cudaFuncAttributeMaxDynamicSharedMemorySize, GSMEM_OUT);
    cudaFuncSetAttribute(flash_mma, cudaFuncAttributeMaxDynamicSharedMemorySize, FSMEM);

    const int NX = NTOK * DMODEL;
    const int NW = DMODEL * DMODEL;
    const int NK = NKVH * HDIM * DMODEL;
    split_bf16<<<NX / 1024, 256>>>(x,  xhi,  xlo,  NX);
    split_bf16<<<NW / 1024, 256>>>(wq, whi,  wlo,  NW);
    split_bf16<<<NK / 1024, 256>>>(wk, whi + (size_t)4096 * DMODEL, wlo + (size_t)4096 * DMODEL, NK);
    split_bf16<<<NK / 1024, 256>>>(wv, whi + (size_t)5120 * DMODEL, wlo + (size_t)5120 * DMODEL, NK);
    split_bf16<<<NW / 1024, 256>>>(wo, wohi, wolo, NW);

    // Fused QKV projection (+RoPE in epilogue) -> hi/lo bf16
    // 128x192 tiles: grid (32, 32) = 1024 tiles -> ~7 waves @148 SMs
    gemm_mma_split<4, 3><<<dim3(NTOK / 128, QKVW / 192), 256, GSMEM_QKV>>>(
        xhi, xlo, whi, wlo, nullptr, qkvhi, qkvlo, cosp, sinp, DMODEL, QKVW);

    // Tensor-core causal GQA attention -> ahi/alo
    flash_mma<<<dim3(SLEN / 128, NHEAD, BATCH), 256, FSMEM>>>(qkvhi, qkvlo, ahi, alo);

    // Output projection -> fp32 d_out
    // 64x256 tiles: grid (64, 16) = 1024 tiles -> ~7 waves
    gemm_mma_split<2, 4><<<dim3(NTOK / 64, DMODEL / 256), 256, GSMEM_OUT>>>(
        ahi, alo, wohi, wolo, outp, nullptr, nullptr, nullptr, nullptr, DMODEL, DMODEL);
}